// round 6
// baseline (speedup 1.0000x reference)
#include <cuda_runtime.h>
#include <cuda_fp16.h>
#include <cstdint>

#define N_NODESC 100000
#define NFEAT    512
#define HID      64
#define NCLS     40
#define N_EDGESC 3200000
#define KPROP    10
#define H2ROW    (NCLS / 2)          // 20 half2 = 80B per node row
#define ROWB     80

#define SCAN_B 512
#define NSB ((N_NODESC + SCAN_B - 1) / SCAN_B)   // 196

typedef unsigned long long ull;

// ---- static scratch (no allocations allowed) ----
__device__ int     g_is64;
__device__ int     g_indeg[N_NODESC];
__device__ float   g_dinv[N_NODESC];
__device__ int     g_offs[N_NODESC + 1];
__device__ int     g_cursor[N_NODESC];
__device__ int     g_bsum[NSB];
__device__ int     g_src[N_EDGESC];
__device__ float   g_h1[(size_t)N_NODESC * HID];
__device__ float   g_h2[(size_t)N_NODESC * NCLS];
__device__ __half2 g_hist[(size_t)(KPROP + 1) * N_NODESC * H2ROW];   // s_0..s_10

// ---- packed fp32x2 helpers ----
__device__ __forceinline__ ull f32x2_fma(ull a, ull b, ull c) {
    ull d;
    asm("fma.rn.f32x2 %0, %1, %2, %3;" : "=l"(d) : "l"(a), "l"(b), "l"(c));
    return d;
}
__device__ __forceinline__ ull f32x2_pack(float lo, float hi) {
    ull d;
    asm("mov.b64 %0, {%1, %2};" : "=l"(d) : "f"(lo), "f"(hi));
    return d;
}
__device__ __forceinline__ float2 f32x2_unpack(ull v) {
    float2 r;
    asm("mov.b64 {%0, %1}, %2;" : "=f"(r.x), "=f"(r.y) : "l"(v));
    return r;
}

// ---------------- dtype detection: int64 edge_index has zero high words ----
__global__ void k_detect(const int* __restrict__ ei) {
    int nz = 0;
    for (int t = threadIdx.x; t < 64; t += 32)
        nz |= (ei[2 * t + 1] != 0);
    unsigned b = __ballot_sync(0xffffffffu, nz);
    if (threadIdx.x == 0) g_is64 = (b == 0u);
}

__device__ __forceinline__ int load_src(const int* ei, int e, int is64) {
    return is64 ? ei[2 * e] : ei[e];
}
__device__ __forceinline__ int load_dst(const int* ei, int e, int is64) {
    return is64 ? ei[2 * (N_EDGESC + e)] : ei[N_EDGESC + e];
}

// ---------------- preprocessing ----------------
__global__ void k_zero() {
    int i = blockIdx.x * blockDim.x + threadIdx.x;
    if (i < N_NODESC) g_indeg[i] = 0;
}

__global__ void k_count(const int* __restrict__ ei) {
    int e = blockIdx.x * blockDim.x + threadIdx.x;
    if (e < N_EDGESC) {
        int dst = load_dst(ei, e, g_is64);
        if ((unsigned)dst < N_NODESC) atomicAdd(&g_indeg[dst], 1);
    }
}

__global__ void k_scan1() {
    __shared__ int s[SCAN_B];
    int i = blockIdx.x * SCAN_B + threadIdx.x;
    int v = (i < N_NODESC) ? g_indeg[i] : 0;
    s[threadIdx.x] = v;
    __syncthreads();
    #pragma unroll
    for (int off = 1; off < SCAN_B; off <<= 1) {
        int t = (threadIdx.x >= off) ? s[threadIdx.x - off] : 0;
        __syncthreads();
        s[threadIdx.x] += t;
        __syncthreads();
    }
    if (i < N_NODESC) g_offs[i] = s[threadIdx.x] - v;
    if (threadIdx.x == SCAN_B - 1) g_bsum[blockIdx.x] = s[SCAN_B - 1];
}

__global__ void k_scan2p() {
    __shared__ int s[256];
    int i = threadIdx.x;
    int v = (i < NSB) ? g_bsum[i] : 0;
    s[i] = v;
    __syncthreads();
    #pragma unroll
    for (int off = 1; off < 256; off <<= 1) {
        int t = (i >= off) ? s[i - off] : 0;
        __syncthreads();
        s[i] += t;
        __syncthreads();
    }
    if (i < NSB) g_bsum[i] = s[i] - v;
    if (i == 255) g_offs[N_NODESC] = s[255];
}

__global__ void k_scan3() {   // offsets + cursor + dinv
    int i = blockIdx.x * blockDim.x + threadIdx.x;
    if (i < N_NODESC) {
        int o = g_offs[i] + g_bsum[i >> 9];
        g_offs[i] = o;
        g_cursor[i] = o;
        g_dinv[i] = rsqrtf((float)(g_indeg[i] + 1));   // +1 self loop
    }
}

__global__ void k_scatter(const int* __restrict__ ei) {
    int e = blockIdx.x * blockDim.x + threadIdx.x;
    if (e < N_EDGESC) {
        int is64 = g_is64;
        int src = load_src(ei, e, is64);
        int dst = load_dst(ei, e, is64);
        if ((unsigned)src >= N_NODESC || (unsigned)dst >= N_NODESC) return;
        int p = atomicAdd(&g_cursor[dst], 1);
        if ((unsigned)p < N_EDGESC) g_src[p] = src;
    }
}

// -------- MLP layer 1 : h1 = relu(x @ w1 + b1), packed f32x2 FFMA2 --------
#define BM 128
#define BN 64
#define BK 32

__global__ __launch_bounds__(256) void k_mlp1(const float* __restrict__ x,
                                              const float* __restrict__ w1,
                                              const float* __restrict__ b1) {
    __shared__ float As[BK][BM + 4];   // transposed A tile; row stride 528B (16B-aligned)
    __shared__ ull   BsP[BK][BN];      // b duplicated as {b,b} pairs
    int tid = threadIdx.x;
    int tc = tid & 15, tr = tid >> 4;
    int r0 = tr * 8, c0 = tc * 4;
    int blockRow = blockIdx.x * BM;

    ull acc2[4][4];
    #pragma unroll
    for (int p = 0; p < 4; p++)
        #pragma unroll
        for (int j = 0; j < 4; j++) acc2[p][j] = 0ull;

    for (int kk = 0; kk < NFEAT; kk += BK) {
        // A tile: 128 rows x 32 cols, stored transposed
        #pragma unroll
        for (int i = 0; i < 4; i++) {
            int f = tid + 256 * i;
            int row = f >> 3;
            int c4 = f & 7;
            int grow = blockRow + row;
            float4 v = make_float4(0.f, 0.f, 0.f, 0.f);
            if (grow < N_NODESC)
                v = *(const float4*)&x[(size_t)grow * NFEAT + kk + c4 * 4];
            As[c4 * 4 + 0][row] = v.x;
            As[c4 * 4 + 1][row] = v.y;
            As[c4 * 4 + 2][row] = v.z;
            As[c4 * 4 + 3][row] = v.w;
        }
        // B tile: 32x64, duplicated pairs
        #pragma unroll
        for (int i = 0; i < 2; i++) {
            int f = tid + 256 * i;        // 0..511 float4 slots
            int row = f >> 4;
            int q = f & 15;
            float4 v = *(const float4*)&w1[(size_t)(kk + row) * HID + q * 4];
            BsP[row][q * 4 + 0] = f32x2_pack(v.x, v.x);
            BsP[row][q * 4 + 1] = f32x2_pack(v.y, v.y);
            BsP[row][q * 4 + 2] = f32x2_pack(v.z, v.z);
            BsP[row][q * 4 + 3] = f32x2_pack(v.w, v.w);
        }
        __syncthreads();
        #pragma unroll 8
        for (int k = 0; k < BK; k++) {
            ulonglong2 a01 = *(const ulonglong2*)&As[k][r0];       // rows (0,1),(2,3)
            ulonglong2 a23 = *(const ulonglong2*)&As[k][r0 + 4];   // rows (4,5),(6,7)
            ulonglong2 b01 = *(const ulonglong2*)&BsP[k][c0];
            ulonglong2 b23 = *(const ulonglong2*)&BsP[k][c0 + 2];
            ull av[4] = {a01.x, a01.y, a23.x, a23.y};
            ull bv[4] = {b01.x, b01.y, b23.x, b23.y};
            #pragma unroll
            for (int p = 0; p < 4; p++)
                #pragma unroll
                for (int j = 0; j < 4; j++)
                    acc2[p][j] = f32x2_fma(av[p], bv[j], acc2[p][j]);
        }
        __syncthreads();
    }
    float4 bb = *(const float4*)&b1[c0];
    float bja[4] = {bb.x, bb.y, bb.z, bb.w};
    #pragma unroll
    for (int p = 0; p < 4; p++) {
        float2 u[4];
        #pragma unroll
        for (int j = 0; j < 4; j++) u[j] = f32x2_unpack(acc2[p][j]);
        int rlo = blockRow + r0 + 2 * p;
        if (rlo < N_NODESC) {
            float4 o;
            o.x = fmaxf(u[0].x + bja[0], 0.f);
            o.y = fmaxf(u[1].x + bja[1], 0.f);
            o.z = fmaxf(u[2].x + bja[2], 0.f);
            o.w = fmaxf(u[3].x + bja[3], 0.f);
            *(float4*)&g_h1[(size_t)rlo * HID + c0] = o;
        }
        if (rlo + 1 < N_NODESC) {
            float4 o;
            o.x = fmaxf(u[0].y + bja[0], 0.f);
            o.y = fmaxf(u[1].y + bja[1], 0.f);
            o.z = fmaxf(u[2].y + bja[2], 0.f);
            o.w = fmaxf(u[3].y + bja[3], 0.f);
            *(float4*)&g_h1[(size_t)(rlo + 1) * HID + c0] = o;
        }
    }
}

// ------- MLP layer 2 : h2 = h1 @ w2 + b2 (fp32, no dinv dependency) -------
__global__ __launch_bounds__(128) void k_mlp2(const float* __restrict__ w2,
                                              const float* __restrict__ b2) {
    __shared__ float ws[HID * NCLS];
    __shared__ float bs[NCLS];
    __shared__ float hs[128 * (HID + 1)];
    int tid = threadIdx.x;
    for (int i = tid; i < HID * NCLS; i += 128) ws[i] = w2[i];
    if (tid < NCLS) bs[tid] = b2[tid];
    int base = blockIdx.x * 128;
    #pragma unroll
    for (int i = 0; i < HID; i++) {
        int f = tid + 128 * i;
        int row = f >> 6, c = f & 63;
        int g = base + row;
        hs[row * (HID + 1) + c] = (g < N_NODESC) ? g_h1[(size_t)g * HID + c] : 0.f;
    }
    __syncthreads();
    int node = base + tid;
    if (node >= N_NODESC) return;
    float acc[NCLS];
    #pragma unroll
    for (int c = 0; c < NCLS; c++) acc[c] = bs[c];
    #pragma unroll 4
    for (int j = 0; j < HID; j++) {
        float hj = hs[tid * (HID + 1) + j];
        #pragma unroll
        for (int c = 0; c < NCLS; c++) acc[c] = fmaf(hj, ws[j * NCLS + c], acc[c]);
    }
    float* o = g_h2 + (size_t)node * NCLS;
    #pragma unroll
    for (int c4 = 0; c4 < NCLS / 4; c4++)
        *(float4*)&o[4 * c4] = make_float4(acc[4 * c4], acc[4 * c4 + 1],
                                           acc[4 * c4 + 2], acc[4 * c4 + 3]);
}

// ------- s_0 = fp16(dinv * h2)  (after preproc+mlp join) -------
__global__ __launch_bounds__(320) void k_scale() {
    int t = blockIdx.x * 320 + threadIdx.x;
    int node = t / 5;
    int lane = t - node * 5;
    if (node >= N_NODESC) return;
    float di = g_dinv[node];
    const float4* h = (const float4*)(g_h2 + (size_t)node * NCLS) + lane * 2;
    float4 v0 = h[0], v1 = h[1];
    uint4 w;
    __half2 hh;
    hh = __floats2half2_rn(di * v0.x, di * v0.y); w.x = *(uint32_t*)&hh;
    hh = __floats2half2_rn(di * v0.z, di * v0.w); w.y = *(uint32_t*)&hh;
    hh = __floats2half2_rn(di * v1.x, di * v1.y); w.z = *(uint32_t*)&hh;
    hh = __floats2half2_rn(di * v1.z, di * v1.w); w.w = *(uint32_t*)&hh;
    *(uint4*)((char*)g_hist + (size_t)node * ROWB + lane * 16) = w;
}

// ------- propagation (s-form): s_{k+1}[d] = dinv[d]^2 * (sum_e s_k[src] + s_k[d])
__global__ __launch_bounds__(320) void k_gather(int kstep) {
    const char* __restrict__ cur = (const char*)(g_hist + (size_t)kstep * N_NODESC * H2ROW);
    char* __restrict__ nxt = (char*)(g_hist + (size_t)(kstep + 1) * N_NODESC * H2ROW);
    int t = blockIdx.x * 320 + threadIdx.x;
    int node = t / 5;
    int lane = t - node * 5;
    if (node >= N_NODESC) return;
    int beg = g_offs[node];
    int end = g_offs[node + 1];
    int lb = lane * 16;
    float a0 = 0.f, a1 = 0.f, a2 = 0.f, a3 = 0.f,
          a4 = 0.f, a5 = 0.f, a6 = 0.f, a7 = 0.f;
    #pragma unroll 4
    for (int e = beg; e < end; ++e) {
        int src = __ldg(&g_src[e]);
        uint4 p = __ldg((const uint4*)(cur + (size_t)src * ROWB + lb));
        float2 v;
        v = __half22float2(*(__half2*)&p.x); a0 += v.x; a1 += v.y;
        v = __half22float2(*(__half2*)&p.y); a2 += v.x; a3 += v.y;
        v = __half22float2(*(__half2*)&p.z); a4 += v.x; a5 += v.y;
        v = __half22float2(*(__half2*)&p.w); a6 += v.x; a7 += v.y;
    }
    float di = g_dinv[node];
    float di2 = di * di;
    uint4 mr = *(const uint4*)(cur + (size_t)node * ROWB + lb);
    float2 m;
    float r[8];
    m = __half22float2(*(__half2*)&mr.x); r[0] = di2 * (a0 + m.x); r[1] = di2 * (a1 + m.y);
    m = __half22float2(*(__half2*)&mr.y); r[2] = di2 * (a2 + m.x); r[3] = di2 * (a3 + m.y);
    m = __half22float2(*(__half2*)&mr.z); r[4] = di2 * (a4 + m.x); r[5] = di2 * (a5 + m.y);
    m = __half22float2(*(__half2*)&mr.w); r[6] = di2 * (a6 + m.x); r[7] = di2 * (a7 + m.y);
    uint4 nw;
    __half2 h;
    h = __floats2half2_rn(r[0], r[1]); nw.x = *(uint32_t*)&h;
    h = __floats2half2_rn(r[2], r[3]); nw.y = *(uint32_t*)&h;
    h = __floats2half2_rn(r[4], r[5]); nw.z = *(uint32_t*)&h;
    h = __floats2half2_rn(r[6], r[7]); nw.w = *(uint32_t*)&h;
    *(uint4*)(nxt + (size_t)node * ROWB + lb) = nw;
}

// ------- final: out = log_softmax( sqrtdeg * sum_k gamma_k * s_k ) -------
__global__ __launch_bounds__(256) void k_final(const float* __restrict__ temp,
                                               float* __restrict__ out) {
    int node = blockIdx.x * blockDim.x + threadIdx.x;
    if (node >= N_NODESC) return;
    float acc[NCLS];
    #pragma unroll
    for (int c = 0; c < NCLS; c++) acc[c] = 0.f;
    const char* base = (const char*)g_hist + (size_t)node * ROWB;
    #pragma unroll
    for (int k = 0; k <= KPROP; k++) {
        float gamma = fmaxf(__ldg(&temp[k]), 0.f);
        const char* row = base + (size_t)k * N_NODESC * ROWB;
        #pragma unroll
        for (int q = 0; q < 5; q++) {
            uint4 p = __ldg((const uint4*)(row + q * 16));
            float2 v;
            v = __half22float2(*(__half2*)&p.x);
            acc[q * 8 + 0] = fmaf(gamma, v.x, acc[q * 8 + 0]);
            acc[q * 8 + 1] = fmaf(gamma, v.y, acc[q * 8 + 1]);
            v = __half22float2(*(__half2*)&p.y);
            acc[q * 8 + 2] = fmaf(gamma, v.x, acc[q * 8 + 2]);
            acc[q * 8 + 3] = fmaf(gamma, v.y, acc[q * 8 + 3]);
            v = __half22float2(*(__half2*)&p.z);
            acc[q * 8 + 4] = fmaf(gamma, v.x, acc[q * 8 + 4]);
            acc[q * 8 + 5] = fmaf(gamma, v.y, acc[q * 8 + 5]);
            v = __half22float2(*(__half2*)&p.w);
            acc[q * 8 + 6] = fmaf(gamma, v.x, acc[q * 8 + 6]);
            acc[q * 8 + 7] = fmaf(gamma, v.y, acc[q * 8 + 7]);
        }
    }
    float sd = 1.0f / g_dinv[node];      // sqrt(deg)
    float mx = -1e30f;
    #pragma unroll
    for (int c = 0; c < NCLS; c++) { acc[c] *= sd; mx = fmaxf(mx, acc[c]); }
    float s = 0.f;
    #pragma unroll
    for (int c = 0; c < NCLS; c++) s += expf(acc[c] - mx);
    float l = mx + logf(s);
    float4* q = (float4*)(out + (size_t)node * NCLS);
    #pragma unroll
    for (int i = 0; i < NCLS / 4; i++) {
        float4 w;
        w.x = acc[4 * i]     - l; w.y = acc[4 * i + 1] - l;
        w.z = acc[4 * i + 2] - l; w.w = acc[4 * i + 3] - l;
        q[i] = w;
    }
}

// ---- persistent stream/event handles (created once on the uncaptured
// correctness call; same launch DAG every call -> deterministic) ----
static cudaStream_t g_s2 = nullptr;
static cudaEvent_t  g_ev0 = nullptr, g_ev1 = nullptr;

extern "C" void kernel_launch(void* const* d_in, const int* in_sizes, int n_in,
                              void* d_out, int out_size) {
    const float* x    = (const float*)d_in[0];
    const int*   ei   = (const int*)d_in[1];     // int32 or int64 (auto-detected)
    const float* w1   = (const float*)d_in[2];
    const float* b1   = (const float*)d_in[3];
    const float* w2   = (const float*)d_in[4];
    const float* b2   = (const float*)d_in[5];
    const float* temp = (const float*)d_in[6];
    float* out = (float*)d_out;

    if (!g_s2) {
        cudaStreamCreateWithFlags(&g_s2, cudaStreamNonBlocking);
        cudaEventCreateWithFlags(&g_ev0, cudaEventDisableTiming);
        cudaEventCreateWithFlags(&g_ev1, cudaEventDisableTiming);
    }

    int nb_nodes = (N_NODESC + 255) / 256;
    int nb_edges = (N_EDGESC + 255) / 256;

    // fork: preprocessing on g_s2, MLP on stream 0
    cudaEventRecord(g_ev0, 0);
    cudaStreamWaitEvent(g_s2, g_ev0, 0);

    k_detect<<<1, 32, 0, g_s2>>>(ei);
    k_zero<<<nb_nodes, 256, 0, g_s2>>>();
    k_count<<<nb_edges, 256, 0, g_s2>>>(ei);
    k_scan1<<<NSB, SCAN_B, 0, g_s2>>>();
    k_scan2p<<<1, 256, 0, g_s2>>>();
    k_scan3<<<nb_nodes, 256, 0, g_s2>>>();
    k_scatter<<<nb_edges, 256, 0, g_s2>>>(ei);
    cudaEventRecord(g_ev1, g_s2);

    k_mlp1<<<(N_NODESC + BM - 1) / BM, 256>>>(x, w1, b1);
    k_mlp2<<<(N_NODESC + 127) / 128, 128>>>(w2, b2);

    // join, then propagate
    cudaStreamWaitEvent(0, g_ev1, 0);
    k_scale<<<(N_NODESC * 5 + 319) / 320, 320>>>();
    for (int k = 0; k < KPROP; k++)
        k_gather<<<(N_NODESC * 5 + 319) / 320, 320>>>(k);
    k_final<<<nb_nodes, 256>>>(temp, out);
}